// round 1
// baseline (speedup 1.0000x reference)
#include <cuda_runtime.h>
#include <math.h>

#define H_DIM 1024
#define F_DIM 4096
#define N_EXP 8
#define MAX_T 4096
#define MAX_A (MAX_T * 2)

// Scratch (allocation-free rule: __device__ globals)
__device__ float g_h[(size_t)MAX_A * F_DIM];   // 134 MB intermediate h
__device__ int   g_counts[N_EXP];
__device__ int   g_offsets[N_EXP + 1];
__device__ int   g_cursor[N_EXP];
__device__ int   g_tok[MAX_A];
__device__ float g_wt[MAX_A];
__device__ int   g_topE[MAX_T * 2];
__device__ float g_topW[MAX_T * 2];

// ---------------------------------------------------------------------------
// 0. zero output + routing counters
// ---------------------------------------------------------------------------
__global__ void zero_kernel(float* __restrict__ out, int n) {
    int i = blockIdx.x * blockDim.x + threadIdx.x;
    if (i < n) out[i] = 0.0f;
    if (blockIdx.x == 0 && threadIdx.x < N_EXP) g_counts[threadIdx.x] = 0;
}

// ---------------------------------------------------------------------------
// 1. router: one warp per token. logits = x @ w_gate, softmax over 8,
//    top-2 (strict > scan == lowest-index tie-break, matching lax.top_k),
//    weights are NON-renormalized full-softmax probs.
// ---------------------------------------------------------------------------
__global__ void router_kernel(const float* __restrict__ x,
                              const float* __restrict__ wg, int T) {
    int warp = (blockIdx.x * blockDim.x + threadIdx.x) >> 5;
    int lane = threadIdx.x & 31;
    if (warp >= T) return;
    const float* xr = x + (size_t)warp * H_DIM;

    float acc[N_EXP];
#pragma unroll
    for (int e = 0; e < N_EXP; e++) acc[e] = 0.0f;

    for (int k = lane; k < H_DIM; k += 32) {
        float xv = xr[k];
        const float* w = wg + (size_t)k * N_EXP;
#pragma unroll
        for (int e = 0; e < N_EXP; e++) acc[e] += xv * w[e];
    }
#pragma unroll
    for (int e = 0; e < N_EXP; e++) {
#pragma unroll
        for (int o = 16; o > 0; o >>= 1)
            acc[e] += __shfl_xor_sync(0xFFFFFFFFu, acc[e], o);
    }
    if (lane == 0) {
        float mx = acc[0];
#pragma unroll
        for (int e = 1; e < N_EXP; e++) mx = fmaxf(mx, acc[e]);
        float p[N_EXP], s = 0.0f;
#pragma unroll
        for (int e = 0; e < N_EXP; e++) { p[e] = __expf(acc[e] - mx); s += p[e]; }
        float inv = 1.0f / s;
        int e0 = 0;
#pragma unroll
        for (int e = 1; e < N_EXP; e++) if (p[e] > p[e0]) e0 = e;
        int e1 = (e0 == 0) ? 1 : 0;
#pragma unroll
        for (int e = 0; e < N_EXP; e++) if (e != e0 && p[e] > p[e1]) e1 = e;

        g_topE[warp * 2 + 0] = e0;
        g_topW[warp * 2 + 0] = p[e0] * inv;
        g_topE[warp * 2 + 1] = e1;
        g_topW[warp * 2 + 1] = p[e1] * inv;
        atomicAdd(&g_counts[e0], 1);
        atomicAdd(&g_counts[e1], 1);
    }
}

// ---------------------------------------------------------------------------
// 2. exclusive prefix sum over 8 counts (single thread, trivial)
// ---------------------------------------------------------------------------
__global__ void offsets_kernel() {
    int s = 0;
    g_offsets[0] = 0;
#pragma unroll
    for (int e = 0; e < N_EXP; e++) {
        g_cursor[e] = s;
        s += g_counts[e];
        g_offsets[e + 1] = s;
    }
}

// ---------------------------------------------------------------------------
// 3. scatter (token, weight) into compact per-expert segments
// ---------------------------------------------------------------------------
__global__ void scatter_kernel(int T) {
    int i = blockIdx.x * blockDim.x + threadIdx.x;
    if (i >= 2 * T) return;
    int e = g_topE[i];
    int pos = atomicAdd(&g_cursor[e], 1);
    g_tok[pos] = i >> 1;
    g_wt[pos]  = g_topW[i];
}

// ---------------------------------------------------------------------------
// 4. gathered gate+up GEMM: h = silu(X_e @ Wg_e) * (X_e @ Wu_e)
//    64x64 tile, TK=16, 256 threads, 4x4 microtile. A tile shared by both.
// ---------------------------------------------------------------------------
#define TM 64
#define TN 64
#define TK 16

__global__ __launch_bounds__(256, 2)
void gateup_kernel(const float* __restrict__ x,
                   const float* __restrict__ wgp,
                   const float* __restrict__ wup) {
    int e   = blockIdx.z;
    int beg = g_offsets[e], end = g_offsets[e + 1];
    int m0  = beg + blockIdx.y * TM;
    if (m0 >= end) return;
    int n0 = blockIdx.x * TN;

    const float* Bg = wgp + (size_t)e * H_DIM * F_DIM + n0;
    const float* Bu = wup + (size_t)e * H_DIM * F_DIM + n0;

    __shared__ float As[TK][68];      // k-major, padded (272B rows, 16B-aligned)
    __shared__ float Bgs[TK][TN];
    __shared__ float Bus[TK][TN];

    int tid = threadIdx.x;
    int tx = tid & 15, ty = tid >> 4;

    // A-load mapping: 4 threads per row, each loads a float4 of k
    int mL = tid >> 2, kq = tid & 3;
    int rowIdx = m0 + mL;
    const float* arow = (rowIdx < end) ? (x + (size_t)g_tok[rowIdx] * H_DIM) : nullptr;
    // B-load mapping: 16 float4 per k-row, 16 k-rows
    int nq = tid & 15, kb = tid >> 4;

    float accg[4][4], accu[4][4];
#pragma unroll
    for (int i = 0; i < 4; i++)
#pragma unroll
        for (int j = 0; j < 4; j++) { accg[i][j] = 0.0f; accu[i][j] = 0.0f; }

    for (int k0 = 0; k0 < H_DIM; k0 += TK) {
        float4 av = make_float4(0.f, 0.f, 0.f, 0.f);
        if (arow) av = *(const float4*)(arow + k0 + kq * 4);
        As[kq * 4 + 0][mL] = av.x;
        As[kq * 4 + 1][mL] = av.y;
        As[kq * 4 + 2][mL] = av.z;
        As[kq * 4 + 3][mL] = av.w;

        *(float4*)&Bgs[kb][nq * 4] = *(const float4*)(Bg + (size_t)(k0 + kb) * F_DIM + nq * 4);
        *(float4*)&Bus[kb][nq * 4] = *(const float4*)(Bu + (size_t)(k0 + kb) * F_DIM + nq * 4);
        __syncthreads();

#pragma unroll
        for (int kk = 0; kk < TK; kk++) {
            float4 a  = *(const float4*)&As[kk][ty * 4];
            float4 bg = *(const float4*)&Bgs[kk][tx * 4];
            float4 bu = *(const float4*)&Bus[kk][tx * 4];
            float am[4] = {a.x, a.y, a.z, a.w};
            float bgm[4] = {bg.x, bg.y, bg.z, bg.w};
            float bum[4] = {bu.x, bu.y, bu.z, bu.w};
#pragma unroll
            for (int i = 0; i < 4; i++)
#pragma unroll
                for (int j = 0; j < 4; j++) {
                    accg[i][j] += am[i] * bgm[j];
                    accu[i][j] += am[i] * bum[j];
                }
        }
        __syncthreads();
    }

#pragma unroll
    for (int i = 0; i < 4; i++) {
        int row = m0 + ty * 4 + i;
        if (row < end) {
            float4 hv;
            float g, u;
            g = accg[i][0]; u = accu[i][0]; hv.x = (g / (1.0f + __expf(-g))) * u;
            g = accg[i][1]; u = accu[i][1]; hv.y = (g / (1.0f + __expf(-g))) * u;
            g = accg[i][2]; u = accu[i][2]; hv.z = (g / (1.0f + __expf(-g))) * u;
            g = accg[i][3]; u = accu[i][3]; hv.w = (g / (1.0f + __expf(-g))) * u;
            *(float4*)&g_h[(size_t)row * F_DIM + n0 + tx * 4] = hv;
        }
    }
}

// ---------------------------------------------------------------------------
// 5. down GEMM: out[token] += (h_e @ Wd_e) * weight   (A rows contiguous)
// ---------------------------------------------------------------------------
__global__ __launch_bounds__(256, 2)
void down_kernel(const float* __restrict__ wdp, float* __restrict__ out) {
    int e   = blockIdx.z;
    int beg = g_offsets[e], end = g_offsets[e + 1];
    int m0  = beg + blockIdx.y * TM;
    if (m0 >= end) return;
    int n0 = blockIdx.x * TN;

    const float* B = wdp + (size_t)e * F_DIM * H_DIM + n0;

    __shared__ float As[TK][68];
    __shared__ float Bs[TK][TN];

    int tid = threadIdx.x;
    int tx = tid & 15, ty = tid >> 4;
    int mL = tid >> 2, kq = tid & 3;
    int rowIdx = m0 + mL;
    const float* arow = (rowIdx < end) ? (g_h + (size_t)rowIdx * F_DIM) : nullptr;
    int nq = tid & 15, kb = tid >> 4;

    float acc[4][4];
#pragma unroll
    for (int i = 0; i < 4; i++)
#pragma unroll
        for (int j = 0; j < 4; j++) acc[i][j] = 0.0f;

    for (int k0 = 0; k0 < F_DIM; k0 += TK) {
        float4 av = make_float4(0.f, 0.f, 0.f, 0.f);
        if (arow) av = *(const float4*)(arow + k0 + kq * 4);
        As[kq * 4 + 0][mL] = av.x;
        As[kq * 4 + 1][mL] = av.y;
        As[kq * 4 + 2][mL] = av.z;
        As[kq * 4 + 3][mL] = av.w;

        *(float4*)&Bs[kb][nq * 4] = *(const float4*)(B + (size_t)(k0 + kb) * H_DIM + nq * 4);
        __syncthreads();

#pragma unroll
        for (int kk = 0; kk < TK; kk++) {
            float4 a = *(const float4*)&As[kk][ty * 4];
            float4 b = *(const float4*)&Bs[kk][tx * 4];
            float am[4] = {a.x, a.y, a.z, a.w};
            float bm[4] = {b.x, b.y, b.z, b.w};
#pragma unroll
            for (int i = 0; i < 4; i++)
#pragma unroll
                for (int j = 0; j < 4; j++) acc[i][j] += am[i] * bm[j];
        }
        __syncthreads();
    }

#pragma unroll
    for (int i = 0; i < 4; i++) {
        int row = m0 + ty * 4 + i;
        if (row < end) {
            float w = g_wt[row];
            float* o = out + (size_t)g_tok[row] * H_DIM + n0 + tx * 4;
            atomicAdd(&o[0], acc[i][0] * w);
            atomicAdd(&o[1], acc[i][1] * w);
            atomicAdd(&o[2], acc[i][2] * w);
            atomicAdd(&o[3], acc[i][3] * w);
        }
    }
}

// ---------------------------------------------------------------------------
extern "C" void kernel_launch(void* const* d_in, const int* in_sizes, int n_in,
                              void* d_out, int out_size) {
    const float* x   = (const float*)d_in[0];
    const float* wg  = (const float*)d_in[1];
    const float* wgp = (const float*)d_in[2];
    const float* wup = (const float*)d_in[3];
    const float* wdp = (const float*)d_in[4];
    float* out = (float*)d_out;

    int T = in_sizes[0] / H_DIM;   // 4096
    int nOut = T * H_DIM;

    zero_kernel<<<(nOut + 255) / 256, 256>>>(out, nOut);
    router_kernel<<<(T + 7) / 8, 256>>>(x, wg, T);
    offsets_kernel<<<1, 1>>>();
    scatter_kernel<<<(2 * T + 255) / 256, 256>>>(T);

    dim3 g2(F_DIM / TN, (T + TM - 1) / TM, N_EXP);
    gateup_kernel<<<g2, 256>>>(x, wgp, wup);

    dim3 g3(H_DIM / TN, (T + TM - 1) / TM, N_EXP);
    down_kernel<<<g3, 256>>>(wdp, out);
}

// round 7
// speedup vs baseline: 3.0510x; 3.0510x over previous
#include <cuda_runtime.h>
#include <cstdint>
#include <math.h>

#define H_DIM 1024
#define F_DIM 4096
#define N_EXP 8
#define MAX_T 4096
#define MAX_A (MAX_T * 2)

#define BM 128
#define BN 128
#define BK 16
#define A_STRIDE 20     // floats per A smem row (16 + 4 pad)
#define B_STRIDE 136    // floats per B smem row (128 + 8 pad)
#define A_F (BM * A_STRIDE)   // 2560 floats
#define B_F (BK * B_STRIDE)   // 2176 floats
#define STAGE_F (A_F + B_F)   // 4736 floats -> 2 stages = 37,888 B

// ---------------------------------------------------------------------------
// Scratch (__device__ globals; referenced ONLY inside device code)
// ---------------------------------------------------------------------------
__device__ float g_xg[(size_t)MAX_A * H_DIM];   // gathered A rows (tf32-rounded)
__device__ float g_g[(size_t)MAX_A * F_DIM];    // gate proj output
__device__ float g_u[(size_t)MAX_A * F_DIM];    // up proj output
__device__ float g_h[(size_t)MAX_A * F_DIM];    // silu(g)*u (tf32-rounded)
__device__ float g_y[(size_t)MAX_A * H_DIM];    // down proj output
__device__ int   g_counts[N_EXP];
__device__ int   g_offsets[N_EXP + 1];
__device__ int   g_cursor[N_EXP];
__device__ int   g_tok[MAX_A];
__device__ int   g_pos[MAX_A];
__device__ int   g_topE[MAX_A];
__device__ float g_topW[MAX_A];

// ---------------------------------------------------------------------------
// helpers
// ---------------------------------------------------------------------------
__device__ __forceinline__ float to_tf32(float x) {
    uint32_t r; asm("cvt.rna.tf32.f32 %0, %1;" : "=r"(r) : "f"(x));
    return __uint_as_float(r);
}
__device__ __forceinline__ uint32_t f2tf(float x) {
    uint32_t r; asm("cvt.rna.tf32.f32 %0, %1;" : "=r"(r) : "f"(x));
    return r;
}
__device__ __forceinline__ uint32_t smem_u32(const void* p) {
    uint32_t a;
    asm("{ .reg .u64 t; cvta.to.shared.u64 t, %1; cvt.u32.u64 %0, t; }" : "=r"(a) : "l"(p));
    return a;
}
__device__ __forceinline__ void cpa16(uint32_t s, const void* g) {
    asm volatile("cp.async.cg.shared.global [%0], [%1], 16;" :: "r"(s), "l"(g));
}
__device__ __forceinline__ void cpa_commit() { asm volatile("cp.async.commit_group;" ::: "memory"); }
template <int N> __device__ __forceinline__ void cpa_wait() {
    asm volatile("cp.async.wait_group %0;" :: "n"(N) : "memory");
}
__device__ __forceinline__ void mma8(float* c, const uint32_t* a, const uint32_t* b) {
    asm volatile(
        "mma.sync.aligned.m16n8k8.row.col.f32.tf32.tf32.f32 "
        "{%0,%1,%2,%3}, {%4,%5,%6,%7}, {%8,%9}, {%0,%1,%2,%3};"
        : "+f"(c[0]), "+f"(c[1]), "+f"(c[2]), "+f"(c[3])
        : "r"(a[0]), "r"(a[1]), "r"(a[2]), "r"(a[3]), "r"(b[0]), "r"(b[1]));
}

// ---------------------------------------------------------------------------
// Routing
// ---------------------------------------------------------------------------
__global__ void zero_kernel() {
    if (threadIdx.x < N_EXP) g_counts[threadIdx.x] = 0;
}

__global__ void router_kernel(const float* __restrict__ x,
                              const float* __restrict__ wg, int T) {
    int warp = (blockIdx.x * blockDim.x + threadIdx.x) >> 5;
    int lane = threadIdx.x & 31;
    if (warp >= T) return;
    const float* xr = x + (size_t)warp * H_DIM;

    float acc[N_EXP];
#pragma unroll
    for (int e = 0; e < N_EXP; e++) acc[e] = 0.0f;
    for (int k = lane; k < H_DIM; k += 32) {
        float xv = xr[k];
        const float* w = wg + (size_t)k * N_EXP;
#pragma unroll
        for (int e = 0; e < N_EXP; e++) acc[e] += xv * w[e];
    }
#pragma unroll
    for (int e = 0; e < N_EXP; e++)
#pragma unroll
        for (int o = 16; o > 0; o >>= 1)
            acc[e] += __shfl_xor_sync(0xFFFFFFFFu, acc[e], o);

    if (lane == 0) {
        float mx = acc[0];
#pragma unroll
        for (int e = 1; e < N_EXP; e++) mx = fmaxf(mx, acc[e]);
        float p[N_EXP], s = 0.0f;
#pragma unroll
        for (int e = 0; e < N_EXP; e++) { p[e] = __expf(acc[e] - mx); s += p[e]; }
        float inv = 1.0f / s;
        int e0 = 0;
#pragma unroll
        for (int e = 1; e < N_EXP; e++) if (p[e] > p[e0]) e0 = e;
        int e1 = (e0 == 0) ? 1 : 0;
#pragma unroll
        for (int e = 0; e < N_EXP; e++) if (e != e0 && p[e] > p[e1]) e1 = e;
        g_topE[warp * 2 + 0] = e0; g_topW[warp * 2 + 0] = p[e0] * inv;
        g_topE[warp * 2 + 1] = e1; g_topW[warp * 2 + 1] = p[e1] * inv;
        atomicAdd(&g_counts[e0], 1);
        atomicAdd(&g_counts[e1], 1);
    }
}

__global__ void offsets_kernel() {
    int s = 0;
    g_offsets[0] = 0;
#pragma unroll
    for (int e = 0; e < N_EXP; e++) {
        g_cursor[e] = s;
        s += g_counts[e];
        g_offsets[e + 1] = s;
    }
}

__global__ void scatter_kernel(int T) {
    int i = blockIdx.x * blockDim.x + threadIdx.x;
    if (i >= 2 * T) return;
    int e = g_topE[i];
    int pos = atomicAdd(&g_cursor[e], 1);
    g_tok[pos] = i >> 1;
    g_pos[i] = pos;
}

// Gather x rows into contiguous per-assignment buffer, rounding to tf32.
__global__ void gather_kernel(const float* __restrict__ x) {
    int a = blockIdx.x;
    int tok = g_tok[a];
    const float4* src = (const float4*)(x + (size_t)tok * H_DIM);
    float4* dst = (float4*)(g_xg + (size_t)a * H_DIM);
    float4 v = src[threadIdx.x];
    v.x = to_tf32(v.x); v.y = to_tf32(v.y); v.z = to_tf32(v.z); v.w = to_tf32(v.w);
    dst[threadIdx.x] = v;
}

// ---------------------------------------------------------------------------
// Generic gathered GEMM: C[m][n] = sum_k A[m][k] * B_e[k][n]
// MODE 0: A=g_xg, C=g_g, K=H, N=F     (gate)
// MODE 1: A=g_xg, C=g_u, K=H, N=F     (up)
// MODE 2: A=g_h,  C=g_y, K=F, N=H     (down)
// Scratch bound in DEVICE code (host cannot reference __device__ symbols).
// ---------------------------------------------------------------------------
template <int MODE>
__global__ __launch_bounds__(256)
void gemm_tf32(const float* __restrict__ B) {
    constexpr int K = (MODE == 2) ? F_DIM : H_DIM;
    constexpr int N = (MODE == 2) ? H_DIM : F_DIM;
    const float* A = (MODE == 2) ? g_h : g_xg;
    float* C = (MODE == 0) ? g_g : (MODE == 1) ? g_u : g_y;

    int e = blockIdx.z;
    int beg = g_offsets[e], end = g_offsets[e + 1];
    int m0 = beg + (int)blockIdx.y * BM;
    if (m0 >= end) return;
    int n0 = blockIdx.x * BN;

    const float* Be = B + (size_t)e * K * N + n0;

    __shared__ float smem[2 * STAGE_F];
    uint32_t sb = smem_u32(smem);

    int tid = threadIdx.x;
    int wid = tid >> 5, lane = tid & 31;
    int wm = (wid & 3) * 32;        // warp M offset (4 warps along M)
    int wn = (wid >> 2) * 64;       // warp N offset (2 warps along N)
    int ar = lane >> 2, ac = lane & 3;

    auto load_chunk = [&](int c) {
        uint32_t base = sb + (uint32_t)(c & 1) * (STAGE_F * 4);
        int k0 = c * BK;
        // A: 128 rows x 16 floats = 512 float4
#pragma unroll
        for (int j = 0; j < 2; j++) {
            int idx = tid + j * 256;
            int row = idx >> 2, q = idx & 3;
            int r = m0 + row; if (r >= end) r = end - 1;
            cpa16(base + (uint32_t)(row * A_STRIDE + q * 4) * 4,
                  A + (size_t)r * K + k0 + q * 4);
        }
        // B: 16 rows x 128 floats = 512 float4
#pragma unroll
        for (int j = 0; j < 2; j++) {
            int idx = tid + j * 256;
            int kr = idx >> 5, q = idx & 31;
            cpa16(base + (uint32_t)(A_F + kr * B_STRIDE + q * 4) * 4,
                  Be + (size_t)(k0 + kr) * N + q * 4);
        }
        cpa_commit();
    };

    float acc[2][8][4];
#pragma unroll
    for (int mf = 0; mf < 2; mf++)
#pragma unroll
        for (int nf = 0; nf < 8; nf++)
#pragma unroll
            for (int i = 0; i < 4; i++) acc[mf][nf][i] = 0.0f;

    constexpr int NCH = K / BK;
    load_chunk(0);

    for (int c = 0; c < NCH; c++) {
        if (c + 1 < NCH) { load_chunk(c + 1); cpa_wait<1>(); }
        else             { cpa_wait<0>(); }
        __syncthreads();

        const float* As = smem + (c & 1) * STAGE_F;
        const float* Bs = As + A_F;
#pragma unroll
        for (int ks = 0; ks < 2; ks++) {
            int k0 = ks * 8;
            uint32_t a[2][4];
#pragma unroll
            for (int mf = 0; mf < 2; mf++) {
                const float* ab = As + (wm + mf * 16 + ar) * A_STRIDE + k0 + ac;
                a[mf][0] = __float_as_uint(ab[0]);
                a[mf][1] = __float_as_uint(ab[8 * A_STRIDE]);
                a[mf][2] = __float_as_uint(ab[4]);
                a[mf][3] = __float_as_uint(ab[8 * A_STRIDE + 4]);
            }
#pragma unroll
            for (int nf = 0; nf < 8; nf++) {
                const float* bb = Bs + (k0 + ac) * B_STRIDE + wn + nf * 8 + ar;
                uint32_t b[2];
                b[0] = f2tf(bb[0]);
                b[1] = f2tf(bb[4 * B_STRIDE]);
#pragma unroll
                for (int mf = 0; mf < 2; mf++) mma8(acc[mf][nf], a[mf], b);
            }
        }
        __syncthreads();
    }

    // epilogue: write C (fp32), guard M
#pragma unroll
    for (int mf = 0; mf < 2; mf++) {
#pragma unroll
        for (int nf = 0; nf < 8; nf++) {
            int row0 = m0 + wm + mf * 16 + ar;
            int col  = n0 + wn + nf * 8 + ac * 2;
            if (row0 < end)
                *(float2*)(C + (size_t)row0 * N + col) =
                    make_float2(acc[mf][nf][0], acc[mf][nf][1]);
            int row1 = row0 + 8;
            if (row1 < end)
                *(float2*)(C + (size_t)row1 * N + col) =
                    make_float2(acc[mf][nf][2], acc[mf][nf][3]);
        }
    }
}

// ---------------------------------------------------------------------------
// h = silu(g) * u, rounded to tf32 (it feeds the down GEMM's A path)
// ---------------------------------------------------------------------------
__global__ void h_kernel() {
    size_t i = (size_t)(blockIdx.x * blockDim.x + threadIdx.x) * 4;
    float4 g = *(const float4*)(g_g + i);
    float4 u = *(const float4*)(g_u + i);
    float4 v;
    v.x = to_tf32((g.x / (1.0f + __expf(-g.x))) * u.x);
    v.y = to_tf32((g.y / (1.0f + __expf(-g.y))) * u.y);
    v.z = to_tf32((g.z / (1.0f + __expf(-g.z))) * u.z);
    v.w = to_tf32((g.w / (1.0f + __expf(-g.w))) * u.w);
    *(float4*)(g_h + i) = v;
}

// ---------------------------------------------------------------------------
// Combine: out[t] = w0 * y[p0] + w1 * y[p1]
// ---------------------------------------------------------------------------
__global__ void combine_kernel(float* __restrict__ out) {
    int t = blockIdx.x;
    int p0 = g_pos[2 * t], p1 = g_pos[2 * t + 1];
    float w0 = g_topW[2 * t], w1 = g_topW[2 * t + 1];
    const float4* y0 = (const float4*)(g_y + (size_t)p0 * H_DIM);
    const float4* y1 = (const float4*)(g_y + (size_t)p1 * H_DIM);
    float4* o = (float4*)(out + (size_t)t * H_DIM);
    float4 a = y0[threadIdx.x], b = y1[threadIdx.x];
    float4 v;
    v.x = w0 * a.x + w1 * b.x;
    v.y = w0 * a.y + w1 * b.y;
    v.z = w0 * a.z + w1 * b.z;
    v.w = w0 * a.w + w1 * b.w;
    o[threadIdx.x] = v;
}

// ---------------------------------------------------------------------------
extern "C" void kernel_launch(void* const* d_in, const int* in_sizes, int n_in,
                              void* d_out, int out_size) {
    const float* x   = (const float*)d_in[0];
    const float* wg  = (const float*)d_in[1];
    const float* wgp = (const float*)d_in[2];
    const float* wup = (const float*)d_in[3];
    const float* wdp = (const float*)d_in[4];
    float* out = (float*)d_out;

    int T = in_sizes[0] / H_DIM;   // 4096

    zero_kernel<<<1, 32>>>();
    router_kernel<<<(T + 7) / 8, 256>>>(x, wg, T);
    offsets_kernel<<<1, 1>>>();
    scatter_kernel<<<(2 * T + 255) / 256, 256>>>(T);
    gather_kernel<<<2 * T, 256>>>(x);

    dim3 gg(F_DIM / BN, (T + BM - 1) / BM, N_EXP);
    gemm_tf32<0><<<gg, 256>>>(wgp);
    gemm_tf32<1><<<gg, 256>>>(wup);

    h_kernel<<<(2 * T) * (F_DIM / 4) / 256, 256>>>();

    dim3 gd(H_DIM / BN, (T + BM - 1) / BM, N_EXP);
    gemm_tf32<2><<<gd, 256>>>(wdp);

    combine_kernel<<<T, 256>>>(out);
}

// round 8
// speedup vs baseline: 4.2519x; 1.3936x over previous
#include <cuda_runtime.h>
#include <cuda_fp16.h>
#include <cstdint>
#include <math.h>

#define H_DIM 1024
#define F_DIM 4096
#define N_EXP 8
#define MAX_T 4096
#define MAX_A (MAX_T * 2)

#define BM 128
#define BN 128
#define BK 32
#define TS 40                 // smem row stride in halves (80 B = 5*16B, conflict-free)
#define TILE_B (BM * TS * 2)  // 10240 bytes per 128x32 half tile
#define GU_STAGE (3 * TILE_B) // A + Bg + Bu = 30720
#define DN_STAGE (2 * TILE_B) // A + B      = 20480

// ---------------------------------------------------------------------------
// Scratch (__device__ globals; referenced ONLY inside device code)
// ---------------------------------------------------------------------------
__device__ __half g_x16[(size_t)MAX_A * H_DIM];            // gathered x rows, fp16
__device__ __half g_h16[(size_t)MAX_A * F_DIM];            // silu(g)*u, fp16
__device__ float  g_y[(size_t)MAX_A * H_DIM];              // down output, fp32
__device__ __half g_wg16[(size_t)N_EXP * F_DIM * H_DIM];   // gate W^T [E][F][H]
__device__ __half g_wu16[(size_t)N_EXP * F_DIM * H_DIM];   // up   W^T [E][F][H]
__device__ __half g_wd16[(size_t)N_EXP * H_DIM * F_DIM];   // down W^T [E][H][F]
__device__ int    g_counts[N_EXP];
__device__ int    g_offsets[N_EXP + 1];
__device__ int    g_cursor[N_EXP];
__device__ int    g_tok[MAX_A];
__device__ int    g_pos[MAX_A];
__device__ int    g_topE[MAX_A];
__device__ float  g_topW[MAX_A];

// ---------------------------------------------------------------------------
// helpers
// ---------------------------------------------------------------------------
__device__ __forceinline__ uint32_t smem_u32(const void* p) {
    uint32_t a;
    asm("{ .reg .u64 t; cvta.to.shared.u64 t, %1; cvt.u32.u64 %0, t; }" : "=r"(a) : "l"(p));
    return a;
}
__device__ __forceinline__ void cpa16(uint32_t s, const void* g) {
    asm volatile("cp.async.cg.shared.global [%0], [%1], 16;" :: "r"(s), "l"(g));
}
__device__ __forceinline__ void cpa_commit() { asm volatile("cp.async.commit_group;" ::: "memory"); }
template <int N> __device__ __forceinline__ void cpa_wait() {
    asm volatile("cp.async.wait_group %0;" :: "n"(N) : "memory");
}
// m16n8k16 fp16 mma, fp32 accumulate
__device__ __forceinline__ void mma16(float* c, const uint32_t* a, const uint32_t* b) {
    asm volatile(
        "mma.sync.aligned.m16n8k16.row.col.f32.f16.f16.f32 "
        "{%0,%1,%2,%3}, {%4,%5,%6,%7}, {%8,%9}, {%0,%1,%2,%3};"
        : "+f"(c[0]), "+f"(c[1]), "+f"(c[2]), "+f"(c[3])
        : "r"(a[0]), "r"(a[1]), "r"(a[2]), "r"(a[3]), "r"(b[0]), "r"(b[1]));
}

// ---------------------------------------------------------------------------
// Routing
// ---------------------------------------------------------------------------
__global__ void zero_kernel() {
    if (threadIdx.x < N_EXP) g_counts[threadIdx.x] = 0;
}

__global__ void router_kernel(const float* __restrict__ x,
                              const float* __restrict__ wg, int T) {
    int warp = (blockIdx.x * blockDim.x + threadIdx.x) >> 5;
    int lane = threadIdx.x & 31;
    if (warp >= T) return;
    const float* xr = x + (size_t)warp * H_DIM;

    float acc[N_EXP];
#pragma unroll
    for (int e = 0; e < N_EXP; e++) acc[e] = 0.0f;
    for (int k = lane; k < H_DIM; k += 32) {
        float xv = xr[k];
        const float* w = wg + (size_t)k * N_EXP;
#pragma unroll
        for (int e = 0; e < N_EXP; e++) acc[e] += xv * w[e];
    }
#pragma unroll
    for (int e = 0; e < N_EXP; e++)
#pragma unroll
        for (int o = 16; o > 0; o >>= 1)
            acc[e] += __shfl_xor_sync(0xFFFFFFFFu, acc[e], o);

    if (lane == 0) {
        float mx = acc[0];
#pragma unroll
        for (int e = 1; e < N_EXP; e++) mx = fmaxf(mx, acc[e]);
        float p[N_EXP], s = 0.0f;
#pragma unroll
        for (int e = 0; e < N_EXP; e++) { p[e] = __expf(acc[e] - mx); s += p[e]; }
        float inv = 1.0f / s;
        int e0 = 0;
#pragma unroll
        for (int e = 1; e < N_EXP; e++) if (p[e] > p[e0]) e0 = e;
        int e1 = (e0 == 0) ? 1 : 0;
#pragma unroll
        for (int e = 0; e < N_EXP; e++) if (e != e0 && p[e] > p[e1]) e1 = e;
        g_topE[warp * 2 + 0] = e0; g_topW[warp * 2 + 0] = p[e0] * inv;
        g_topE[warp * 2 + 1] = e1; g_topW[warp * 2 + 1] = p[e1] * inv;
        atomicAdd(&g_counts[e0], 1);
        atomicAdd(&g_counts[e1], 1);
    }
}

__global__ void offsets_kernel() {
    int s = 0;
    g_offsets[0] = 0;
#pragma unroll
    for (int e = 0; e < N_EXP; e++) {
        g_cursor[e] = s;
        s += g_counts[e];
        g_offsets[e + 1] = s;
    }
}

__global__ void scatter_kernel(int T) {
    int i = blockIdx.x * blockDim.x + threadIdx.x;
    if (i >= 2 * T) return;
    int e = g_topE[i];
    int pos = atomicAdd(&g_cursor[e], 1);
    g_tok[pos] = i >> 1;
    g_pos[i] = pos;
}

// Gather x rows into contiguous fp16 buffer.
__global__ void gather_kernel(const float* __restrict__ x) {
    int a = blockIdx.x;
    int tok = g_tok[a];
    const float4* src = (const float4*)(x + (size_t)tok * H_DIM);
    float4 v = src[threadIdx.x];
    __half2* dst = (__half2*)(g_x16 + (size_t)a * H_DIM) + threadIdx.x * 2;
    dst[0] = __floats2half2_rn(v.x, v.y);
    dst[1] = __floats2half2_rn(v.z, v.w);
}

// ---------------------------------------------------------------------------
// Weight transpose+convert: fp32 [E][R][C] -> fp16 [E][C][R]
// MODE 0: w_gate_proj -> g_wg16 (R=H, C=F)
// MODE 1: w_up_proj   -> g_wu16 (R=H, C=F)
// MODE 2: w_down_proj -> g_wd16 (R=F, C=H)
// ---------------------------------------------------------------------------
template <int MODE>
__global__ void transconv_kernel(const float* __restrict__ in) {
    constexpr int R = (MODE == 2) ? F_DIM : H_DIM;
    constexpr int C = (MODE == 2) ? H_DIM : F_DIM;
    __half* out = (MODE == 0) ? g_wg16 : (MODE == 1) ? g_wu16 : g_wd16;

    __shared__ float tile[32][33];
    size_t mat = (size_t)blockIdx.z * R * C;
    const float* I = in + mat;
    __half* O = out + mat;
    int c0 = blockIdx.x * 32, r0 = blockIdx.y * 32;
    int tx = threadIdx.x;
#pragma unroll
    for (int j = threadIdx.y; j < 32; j += 8)
        tile[j][tx] = I[(size_t)(r0 + j) * C + c0 + tx];
    __syncthreads();
#pragma unroll
    for (int j = threadIdx.y; j < 32; j += 8)
        O[(size_t)(c0 + j) * R + r0 + tx] = __float2half(tile[tx][j]);
}

// ---------------------------------------------------------------------------
// Fused gate+up GEMM (fp16): h = silu(Xg @ Wg^T) * (Xg @ Wu^T)
// A [m][k] k-major, B [n][k] k-major; both 128x32 half tiles, stride 40 halves.
// ---------------------------------------------------------------------------
__global__ __launch_bounds__(256)
void gateup_kernel() {
    constexpr int K = H_DIM, NCH = K / BK;

    int e = blockIdx.z;
    int beg = g_offsets[e], end = g_offsets[e + 1];
    int m0 = beg + (int)blockIdx.y * BM;
    if (m0 >= end) return;
    int n0 = blockIdx.x * BN;

    const __half* Bg = g_wg16 + (size_t)e * F_DIM * H_DIM + (size_t)n0 * K;
    const __half* Bu = g_wu16 + (size_t)e * F_DIM * H_DIM + (size_t)n0 * K;

    extern __shared__ char smem[];
    uint32_t sb = smem_u32(smem);

    int tid = threadIdx.x;
    int wid = tid >> 5, lane = tid & 31;
    int wm = (wid & 3) * 32;      // 4 warps along M
    int wn = (wid >> 2) * 64;     // 2 warps along N
    int gr = lane >> 2, qc = (lane & 3) * 2;

    auto load_chunk = [&](int c) {
        uint32_t base = sb + (uint32_t)(c & 1) * GU_STAGE;
        int k0 = c * BK;
#pragma unroll
        for (int j = 0; j < 2; j++) {
            int idx = tid + j * 256;
            int row = idx >> 2, q = idx & 3;
            int r = m0 + row; if (r >= end) r = end - 1;
            cpa16(base + (uint32_t)(row * 80 + q * 16),
                  g_x16 + (size_t)r * K + k0 + q * 8);
        }
#pragma unroll
        for (int j = 0; j < 2; j++) {
            int idx = tid + j * 256;
            int n = idx >> 2, q = idx & 3;
            uint32_t so = (uint32_t)(n * 80 + q * 16);
            size_t go = (size_t)n * K + k0 + q * 8;
            cpa16(base + TILE_B + so, Bg + go);
            cpa16(base + 2 * TILE_B + so, Bu + go);
        }
        cpa_commit();
    };

    float accg[2][8][4], accu[2][8][4];
#pragma unroll
    for (int mf = 0; mf < 2; mf++)
#pragma unroll
        for (int nf = 0; nf < 8; nf++)
#pragma unroll
            for (int i = 0; i < 4; i++) { accg[mf][nf][i] = 0.0f; accu[mf][nf][i] = 0.0f; }

    load_chunk(0);

    for (int c = 0; c < NCH; c++) {
        if (c + 1 < NCH) { load_chunk(c + 1); cpa_wait<1>(); }
        else             { cpa_wait<0>(); }
        __syncthreads();

        const char* st = smem + (c & 1) * GU_STAGE;
        const __half* As  = (const __half*)st;
        const __half* Bgs = (const __half*)(st + TILE_B);
        const __half* Bus = (const __half*)(st + 2 * TILE_B);

#pragma unroll
        for (int ks = 0; ks < 2; ks++) {
            int kb = ks * 16;
            uint32_t a[2][4];
#pragma unroll
            for (int mf = 0; mf < 2; mf++) {
                const __half* ab = As + (wm + mf * 16 + gr) * TS + kb + qc;
                a[mf][0] = *(const uint32_t*)(ab);
                a[mf][1] = *(const uint32_t*)(ab + 8 * TS);
                a[mf][2] = *(const uint32_t*)(ab + 8);
                a[mf][3] = *(const uint32_t*)(ab + 8 * TS + 8);
            }
#pragma unroll
            for (int nf = 0; nf < 8; nf++) {
                const __half* bgb = Bgs + (wn + nf * 8 + gr) * TS + kb + qc;
                uint32_t b[2];
                b[0] = *(const uint32_t*)(bgb);
                b[1] = *(const uint32_t*)(bgb + 8);
#pragma unroll
                for (int mf = 0; mf < 2; mf++) mma16(accg[mf][nf], a[mf], b);
                const __half* bub = Bus + (wn + nf * 8 + gr) * TS + kb + qc;
                b[0] = *(const uint32_t*)(bub);
                b[1] = *(const uint32_t*)(bub + 8);
#pragma unroll
                for (int mf = 0; mf < 2; mf++) mma16(accu[mf][nf], a[mf], b);
            }
        }
        __syncthreads();
    }

    // epilogue: h = silu(g) * u, fp16
#pragma unroll
    for (int mf = 0; mf < 2; mf++) {
#pragma unroll
        for (int nf = 0; nf < 8; nf++) {
            int row0 = m0 + wm + mf * 16 + gr;
            int col  = n0 + wn + nf * 8 + qc;
            if (row0 < end) {
                float gv0 = accg[mf][nf][0], gv1 = accg[mf][nf][1];
                float h0 = (gv0 / (1.0f + __expf(-gv0))) * accu[mf][nf][0];
                float h1 = (gv1 / (1.0f + __expf(-gv1))) * accu[mf][nf][1];
                *(__half2*)(g_h16 + (size_t)row0 * F_DIM + col) = __floats2half2_rn(h0, h1);
            }
            int row1 = row0 + 8;
            if (row1 < end) {
                float gv2 = accg[mf][nf][2], gv3 = accg[mf][nf][3];
                float h2 = (gv2 / (1.0f + __expf(-gv2))) * accu[mf][nf][2];
                float h3 = (gv3 / (1.0f + __expf(-gv3))) * accu[mf][nf][3];
                *(__half2*)(g_h16 + (size_t)row1 * F_DIM + col) = __floats2half2_rn(h2, h3);
            }
        }
    }
}

// ---------------------------------------------------------------------------
// Down GEMM (fp16): y = h @ Wd^T   (K = 4096, N = 1024)
// ---------------------------------------------------------------------------
__global__ __launch_bounds__(256)
void down_kernel() {
    constexpr int K = F_DIM, N = H_DIM, NCH = K / BK;

    int e = blockIdx.z;
    int beg = g_offsets[e], end = g_offsets[e + 1];
    int m0 = beg + (int)blockIdx.y * BM;
    if (m0 >= end) return;
    int n0 = blockIdx.x * BN;

    const __half* Bm = g_wd16 + (size_t)e * H_DIM * F_DIM + (size_t)n0 * K;

    __shared__ __align__(16) char smem[2 * DN_STAGE];
    uint32_t sb = smem_u32(smem);

    int tid = threadIdx.x;
    int wid = tid >> 5, lane = tid & 31;
    int wm = (wid & 3) * 32;
    int wn = (wid >> 2) * 64;
    int gr = lane >> 2, qc = (lane & 3) * 2;

    auto load_chunk = [&](int c) {
        uint32_t base = sb + (uint32_t)(c & 1) * DN_STAGE;
        int k0 = c * BK;
#pragma unroll
        for (int j = 0; j < 2; j++) {
            int idx = tid + j * 256;
            int row = idx >> 2, q = idx & 3;
            int r = m0 + row; if (r >= end) r = end - 1;
            cpa16(base + (uint32_t)(row * 80 + q * 16),
                  g_h16 + (size_t)r * K + k0 + q * 8);
        }
#pragma unroll
        for (int j = 0; j < 2; j++) {
            int idx = tid + j * 256;
            int n = idx >> 2, q = idx & 3;
            cpa16(base + TILE_B + (uint32_t)(n * 80 + q * 16),
                  Bm + (size_t)n * K + k0 + q * 8);
        }
        cpa_commit();
    };

    float acc[2][8][4];
#pragma unroll
    for (int mf = 0; mf < 2; mf++)
#pragma unroll
        for (int nf = 0; nf < 8; nf++)
#pragma unroll
            for (int i = 0; i < 4; i++) acc[mf][nf][i] = 0.0f;

    load_chunk(0);

    for (int c = 0; c < NCH; c++) {
        if (c + 1 < NCH) { load_chunk(c + 1); cpa_wait<1>(); }
        else             { cpa_wait<0>(); }
        __syncthreads();

        const char* st = smem + (c & 1) * DN_STAGE;
        const __half* As = (const __half*)st;
        const __half* Bs = (const __half*)(st + TILE_B);

#pragma unroll
        for (int ks = 0; ks < 2; ks++) {
            int kb = ks * 16;
            uint32_t a[2][4];
#pragma unroll
            for (int mf = 0; mf < 2; mf++) {
                const __half* ab = As + (wm + mf * 16 + gr) * TS + kb + qc;
                a[mf][0] = *(const uint32_t*)(ab);
                a[mf][1] = *(const uint32_t*)(ab + 8 * TS);
                a[mf][2] = *(const uint32_t*)(ab + 8);
                a[mf][3] = *(const uint32_t*)(ab + 8 * TS + 8);
            }
#pragma unroll
            for (int nf = 0; nf < 8; nf++) {
                const __half* bb = Bs + (wn + nf * 8 + gr) * TS + kb + qc;
                uint32_t b[2];
                b[0] = *(const uint32_t*)(bb);
                b[1] = *(const uint32_t*)(bb + 8);
#pragma unroll
                for (int mf = 0; mf < 2; mf++) mma16(acc[mf][nf], a[mf], b);
            }
        }
        __syncthreads();
    }

#pragma unroll
    for (int mf = 0; mf < 2; mf++) {
#pragma unroll
        for (int nf = 0; nf < 8; nf++) {
            int row0 = m0 + wm + mf * 16 + gr;
            int col  = n0 + wn + nf * 8 + qc;
            if (row0 < end)
                *(float2*)(g_y + (size_t)row0 * N + col) =
                    make_float2(acc[mf][nf][0], acc[mf][nf][1]);
            int row1 = row0 + 8;
            if (row1 < end)
                *(float2*)(g_y + (size_t)row1 * N + col) =
                    make_float2(acc[mf][nf][2], acc[mf][nf][3]);
        }
    }
}

// ---------------------------------------------------------------------------
// Combine: out[t] = w0 * y[p0] + w1 * y[p1]
// ---------------------------------------------------------------------------
__global__ void combine_kernel(float* __restrict__ out) {
    int t = blockIdx.x;
    int p0 = g_pos[2 * t], p1 = g_pos[2 * t + 1];
    float w0 = g_topW[2 * t], w1 = g_topW[2 * t + 1];
    const float4* y0 = (const float4*)(g_y + (size_t)p0 * H_DIM);
    const float4* y1 = (const float4*)(g_y + (size_t)p1 * H_DIM);
    float4* o = (float4*)(out + (size_t)t * H_DIM);
    float4 a = y0[threadIdx.x], b = y1[threadIdx.x];
    float4 v;
    v.x = w0 * a.x + w1 * b.x;
    v.y = w0 * a.y + w1 * b.y;
    v.z = w0 * a.z + w1 * b.z;
    v.w = w0 * a.w + w1 * b.w;
    o[threadIdx.x] = v;
}

// ---------------------------------------------------------------------------
extern "C" void kernel_launch(void* const* d_in, const int* in_sizes, int n_in,
                              void* d_out, int out_size) {
    const float* x   = (const float*)d_in[0];
    const float* wg  = (const float*)d_in[1];
    const float* wgp = (const float*)d_in[2];
    const float* wup = (const float*)d_in[3];
    const float* wdp = (const float*)d_in[4];
    float* out = (float*)d_out;

    int T = in_sizes[0] / H_DIM;   // 4096

    cudaFuncSetAttribute(gateup_kernel,
                         cudaFuncAttributeMaxDynamicSharedMemorySize, 2 * GU_STAGE);

    zero_kernel<<<1, 32>>>();
    router_kernel<<<(T + 7) / 8, 256>>>(x, wg, T);
    offsets_kernel<<<1, 1>>>();
    scatter_kernel<<<(2 * T + 255) / 256, 256>>>(T);
    gather_kernel<<<2 * T, 256>>>(x);

    {
        dim3 blk(32, 8);
        dim3 ggu(F_DIM / 32, H_DIM / 32, N_EXP);
        transconv_kernel<0><<<ggu, blk>>>(wgp);
        transconv_kernel<1><<<ggu, blk>>>(wup);
        dim3 gd(H_DIM / 32, F_DIM / 32, N_EXP);
        transconv_kernel<2><<<gd, blk>>>(wdp);
    }

    dim3 g1(F_DIM / BN, (T + BM - 1) / BM, N_EXP);
    gateup_kernel<<<g1, 256, 2 * GU_STAGE>>>();

    dim3 g2(H_DIM / BN, (T + BM - 1) / BM, N_EXP);
    down_kernel<<<g2, 256>>>();

    combine_kernel<<<T, 256>>>(out);
}

// round 9
// speedup vs baseline: 4.9458x; 1.1632x over previous
#include <cuda_runtime.h>
#include <cuda_fp16.h>
#include <cstdint>
#include <math.h>

#define H_DIM 1024
#define F_DIM 4096
#define N_EXP 8
#define MAX_T 4096
#define MAX_A (MAX_T * 2)

#define BM 128
#define BN 128
#define BK 32
#define TS 40                     // A smem stride (halves): 80 B, conflict-free
#define BS 136                    // B smem stride (halves): 272 B, conflict-free for trans
#define A_TILE_B (BM * TS * 2)    // 10240 B
#define B_TILE_B (BK * BS * 2)    // 8704 B
#define GU_STAGE (A_TILE_B + 2 * B_TILE_B)   // 27648
#define DN_STAGE (A_TILE_B + B_TILE_B)       // 18944
#define NSTAGE 3

// ---------------------------------------------------------------------------
// Scratch (__device__ globals; referenced ONLY inside device code)
// ---------------------------------------------------------------------------
__device__ __half g_x16[(size_t)MAX_A * H_DIM];            // gathered x rows, fp16
__device__ __half g_h16[(size_t)MAX_A * F_DIM];            // silu(g)*u, fp16
__device__ float  g_y[(size_t)MAX_A * H_DIM];              // down output, fp32
__device__ __half g_wg16[(size_t)N_EXP * H_DIM * F_DIM];   // gate W fp16 [E][K][N]
__device__ __half g_wu16[(size_t)N_EXP * H_DIM * F_DIM];   // up   W fp16 [E][K][N]
__device__ __half g_wd16[(size_t)N_EXP * F_DIM * H_DIM];   // down W fp16 [E][K][N]
__device__ int    g_counts[N_EXP];
__device__ int    g_offsets[N_EXP + 1];
__device__ int    g_cursor[N_EXP];
__device__ int    g_tok[MAX_A];
__device__ int    g_pos[MAX_A];
__device__ int    g_topE[MAX_A];
__device__ float  g_topW[MAX_A];

// ---------------------------------------------------------------------------
// helpers
// ---------------------------------------------------------------------------
__device__ __forceinline__ uint32_t smem_u32(const void* p) {
    uint32_t a;
    asm("{ .reg .u64 t; cvta.to.shared.u64 t, %1; cvt.u32.u64 %0, t; }" : "=r"(a) : "l"(p));
    return a;
}
__device__ __forceinline__ void cpa16(uint32_t s, const void* g) {
    asm volatile("cp.async.cg.shared.global [%0], [%1], 16;" :: "r"(s), "l"(g));
}
__device__ __forceinline__ void cpa_commit() { asm volatile("cp.async.commit_group;" ::: "memory"); }
template <int N> __device__ __forceinline__ void cpa_wait() {
    asm volatile("cp.async.wait_group %0;" :: "n"(N) : "memory");
}
__device__ __forceinline__ void mma16(float* c, const uint32_t* a, const uint32_t* b) {
    asm volatile(
        "mma.sync.aligned.m16n8k16.row.col.f32.f16.f16.f32 "
        "{%0,%1,%2,%3}, {%4,%5,%6,%7}, {%8,%9}, {%0,%1,%2,%3};"
        : "+f"(c[0]), "+f"(c[1]), "+f"(c[2]), "+f"(c[3])
        : "r"(a[0]), "r"(a[1]), "r"(a[2]), "r"(a[3]), "r"(b[0]), "r"(b[1]));
}
__device__ __forceinline__ void ldm_x4(uint32_t* r, uint32_t a) {
    asm volatile("ldmatrix.sync.aligned.m8n8.x4.shared.b16 {%0,%1,%2,%3}, [%4];"
        : "=r"(r[0]), "=r"(r[1]), "=r"(r[2]), "=r"(r[3]) : "r"(a));
}
__device__ __forceinline__ void ldm_x4_t(uint32_t* r, uint32_t a) {
    asm volatile("ldmatrix.sync.aligned.m8n8.x4.trans.shared.b16 {%0,%1,%2,%3}, [%4];"
        : "=r"(r[0]), "=r"(r[1]), "=r"(r[2]), "=r"(r[3]) : "r"(a));
}

// ---------------------------------------------------------------------------
// Routing
// ---------------------------------------------------------------------------
__global__ void zero_kernel() {
    if (threadIdx.x < N_EXP) g_counts[threadIdx.x] = 0;
}

__global__ void router_kernel(const float* __restrict__ x,
                              const float* __restrict__ wg, int T) {
    int warp = (blockIdx.x * blockDim.x + threadIdx.x) >> 5;
    int lane = threadIdx.x & 31;
    if (warp >= T) return;
    const float* xr = x + (size_t)warp * H_DIM;

    float acc[N_EXP];
#pragma unroll
    for (int e = 0; e < N_EXP; e++) acc[e] = 0.0f;
    for (int k = lane; k < H_DIM; k += 32) {
        float xv = xr[k];
        const float* w = wg + (size_t)k * N_EXP;
#pragma unroll
        for (int e = 0; e < N_EXP; e++) acc[e] += xv * w[e];
    }
#pragma unroll
    for (int e = 0; e < N_EXP; e++)
#pragma unroll
        for (int o = 16; o > 0; o >>= 1)
            acc[e] += __shfl_xor_sync(0xFFFFFFFFu, acc[e], o);

    if (lane == 0) {
        float mx = acc[0];
#pragma unroll
        for (int e = 1; e < N_EXP; e++) mx = fmaxf(mx, acc[e]);
        float p[N_EXP], s = 0.0f;
#pragma unroll
        for (int e = 0; e < N_EXP; e++) { p[e] = __expf(acc[e] - mx); s += p[e]; }
        float inv = 1.0f / s;
        int e0 = 0;
#pragma unroll
        for (int e = 1; e < N_EXP; e++) if (p[e] > p[e0]) e0 = e;
        int e1 = (e0 == 0) ? 1 : 0;
#pragma unroll
        for (int e = 0; e < N_EXP; e++) if (e != e0 && p[e] > p[e1]) e1 = e;
        g_topE[warp * 2 + 0] = e0; g_topW[warp * 2 + 0] = p[e0] * inv;
        g_topE[warp * 2 + 1] = e1; g_topW[warp * 2 + 1] = p[e1] * inv;
        atomicAdd(&g_counts[e0], 1);
        atomicAdd(&g_counts[e1], 1);
    }
}

__global__ void offsets_kernel() {
    int s = 0;
    g_offsets[0] = 0;
#pragma unroll
    for (int e = 0; e < N_EXP; e++) {
        g_cursor[e] = s;
        s += g_counts[e];
        g_offsets[e + 1] = s;
    }
}

__global__ void scatter_kernel(int T) {
    int i = blockIdx.x * blockDim.x + threadIdx.x;
    if (i >= 2 * T) return;
    int e = g_topE[i];
    int pos = atomicAdd(&g_cursor[e], 1);
    g_tok[pos] = i >> 1;
    g_pos[i] = pos;
}

// Gather x rows into contiguous fp16 buffer.
__global__ void gather_kernel(const float* __restrict__ x) {
    int a = blockIdx.x;
    int tok = g_tok[a];
    const float4* src = (const float4*)(x + (size_t)tok * H_DIM);
    float4 v = src[threadIdx.x];
    __half2* dst = (__half2*)(g_x16 + (size_t)a * H_DIM) + threadIdx.x * 2;
    dst[0] = __floats2half2_rn(v.x, v.y);
    dst[1] = __floats2half2_rn(v.z, v.w);
}

// ---------------------------------------------------------------------------
// Streaming fp32 -> fp16 convert (no transpose; layout stays [E][K][N])
// MODE 0: gate, 1: up, 2: down. Each thread converts 8 floats.
// ---------------------------------------------------------------------------
template <int MODE>
__global__ void convert_kernel(const float4* __restrict__ in) {
    __half* out = (MODE == 0) ? g_wg16 : (MODE == 1) ? g_wu16 : g_wd16;
    size_t i = (size_t)blockIdx.x * blockDim.x + threadIdx.x;
    float4 v0 = in[2 * i], v1 = in[2 * i + 1];
    __half2 h[4];
    h[0] = __floats2half2_rn(v0.x, v0.y);
    h[1] = __floats2half2_rn(v0.z, v0.w);
    h[2] = __floats2half2_rn(v1.x, v1.y);
    h[3] = __floats2half2_rn(v1.z, v1.w);
    *(uint4*)(out + i * 8) = *(const uint4*)h;
}

// ---------------------------------------------------------------------------
// Fused gate+up GEMM (fp16, ldmatrix): h = silu(Xg @ Wg) * (Xg @ Wu)
// A [m][k] k-major smem; B [k][n] n-major smem, fragments via ldmatrix.trans.
// ---------------------------------------------------------------------------
__global__ __launch_bounds__(256)
void gateup_kernel() {
    constexpr int K = H_DIM, N = F_DIM, NCH = K / BK;

    int e = blockIdx.z;
    int beg = g_offsets[e], end = g_offsets[e + 1];
    int m0 = beg + (int)blockIdx.y * BM;
    if (m0 >= end) return;
    int n0 = blockIdx.x * BN;

    const __half* Bg = g_wg16 + (size_t)e * K * N + n0;
    const __half* Bu = g_wu16 + (size_t)e * K * N + n0;

    extern __shared__ char smem[];
    uint32_t sb = smem_u32(smem);

    int tid = threadIdx.x;
    int wid = tid >> 5, lane = tid & 31;
    int wm = (wid & 3) * 32;      // 4 warps along M
    int wn = (wid >> 2) * 64;     // 2 warps along N
    int gr = lane >> 2, qc = (lane & 3) * 2;

    // ldmatrix lane addressing (precomputed pieces)
    int a_row = (lane & 15), a_koff = (lane >> 4) << 3;          // A x4
    int b_krow = (lane & 7) + (((lane >> 3) & 1) << 3);          // B x4 trans
    int b_noff = (lane >> 4) << 3;

    auto load_chunk = [&](int c) {
        uint32_t base = sb + (uint32_t)(c % NSTAGE) * GU_STAGE;
        int k0 = c * BK;
#pragma unroll
        for (int j = 0; j < 2; j++) {
            int idx = tid + j * 256;
            int row = idx >> 2, q = idx & 3;
            int r = m0 + row; if (r >= end) r = end - 1;
            cpa16(base + (uint32_t)(row * (TS * 2) + q * 16),
                  g_x16 + (size_t)r * K + k0 + q * 8);
        }
#pragma unroll
        for (int j = 0; j < 2; j++) {
            int idx = tid + j * 256;
            int kr = idx >> 4, q = idx & 15;
            uint32_t so = (uint32_t)(kr * (BS * 2) + q * 16);
            size_t go = (size_t)(k0 + kr) * N + q * 8;
            cpa16(base + A_TILE_B + so, Bg + go);
            cpa16(base + A_TILE_B + B_TILE_B + so, Bu + go);
        }
        cpa_commit();
    };

    float accg[2][8][4], accu[2][8][4];
#pragma unroll
    for (int mf = 0; mf < 2; mf++)
#pragma unroll
        for (int nf = 0; nf < 8; nf++)
#pragma unroll
            for (int i = 0; i < 4; i++) { accg[mf][nf][i] = 0.0f; accu[mf][nf][i] = 0.0f; }

    load_chunk(0);
    load_chunk(1);

    for (int c = 0; c < NCH; c++) {
        if (c + 2 < NCH)      { load_chunk(c + 2); cpa_wait<2>(); }
        else if (c + 1 < NCH) { cpa_wait<1>(); }
        else                  { cpa_wait<0>(); }
        __syncthreads();

        uint32_t stA  = sb + (uint32_t)(c % NSTAGE) * GU_STAGE;
        uint32_t stBg = stA + A_TILE_B;
        uint32_t stBu = stBg + B_TILE_B;

#pragma unroll
        for (int ks = 0; ks < 2; ks++) {
            int kb = ks * 16;
            uint32_t a[2][4];
#pragma unroll
            for (int mf = 0; mf < 2; mf++)
                ldm_x4(a[mf], stA + (uint32_t)(((wm + mf * 16 + a_row) * TS + kb + a_koff) * 2));

            int bk = kb + b_krow;
#pragma unroll
            for (int pf = 0; pf < 4; pf++) {
                int bn = wn + pf * 16 + b_noff;
                uint32_t bg[4], bu[4];
                ldm_x4_t(bg, stBg + (uint32_t)((bk * BS + bn) * 2));
                ldm_x4_t(bu, stBu + (uint32_t)((bk * BS + bn) * 2));
#pragma unroll
                for (int sub = 0; sub < 2; sub++) {
                    int nf = pf * 2 + sub;
#pragma unroll
                    for (int mf = 0; mf < 2; mf++) {
                        mma16(accg[mf][nf], a[mf], bg + sub * 2);
                        mma16(accu[mf][nf], a[mf], bu + sub * 2);
                    }
                }
            }
        }
        __syncthreads();
    }

    // epilogue: h = silu(g) * u, fp16
#pragma unroll
    for (int mf = 0; mf < 2; mf++) {
#pragma unroll
        for (int nf = 0; nf < 8; nf++) {
            int row0 = m0 + wm + mf * 16 + gr;
            int col  = n0 + wn + nf * 8 + qc;
            if (row0 < end) {
                float gv0 = accg[mf][nf][0], gv1 = accg[mf][nf][1];
                float h0 = (gv0 / (1.0f + __expf(-gv0))) * accu[mf][nf][0];
                float h1 = (gv1 / (1.0f + __expf(-gv1))) * accu[mf][nf][1];
                *(__half2*)(g_h16 + (size_t)row0 * F_DIM + col) = __floats2half2_rn(h0, h1);
            }
            int row1 = row0 + 8;
            if (row1 < end) {
                float gv2 = accg[mf][nf][2], gv3 = accg[mf][nf][3];
                float h2 = (gv2 / (1.0f + __expf(-gv2))) * accu[mf][nf][2];
                float h3 = (gv3 / (1.0f + __expf(-gv3))) * accu[mf][nf][3];
                *(__half2*)(g_h16 + (size_t)row1 * F_DIM + col) = __floats2half2_rn(h2, h3);
            }
        }
    }
}

// ---------------------------------------------------------------------------
// Down GEMM (fp16, ldmatrix): y = h @ Wd   (K = 4096, N = 1024)
// ---------------------------------------------------------------------------
__global__ __launch_bounds__(256)
void down_kernel() {
    constexpr int K = F_DIM, N = H_DIM, NCH = K / BK;

    int e = blockIdx.z;
    int beg = g_offsets[e], end = g_offsets[e + 1];
    int m0 = beg + (int)blockIdx.y * BM;
    if (m0 >= end) return;
    int n0 = blockIdx.x * BN;

    const __half* Bm = g_wd16 + (size_t)e * K * N + n0;

    extern __shared__ char smem[];
    uint32_t sb = smem_u32(smem);

    int tid = threadIdx.x;
    int wid = tid >> 5, lane = tid & 31;
    int wm = (wid & 3) * 32;
    int wn = (wid >> 2) * 64;
    int gr = lane >> 2, qc = (lane & 3) * 2;

    int a_row = (lane & 15), a_koff = (lane >> 4) << 3;
    int b_krow = (lane & 7) + (((lane >> 3) & 1) << 3);
    int b_noff = (lane >> 4) << 3;

    auto load_chunk = [&](int c) {
        uint32_t base = sb + (uint32_t)(c % NSTAGE) * DN_STAGE;
        int k0 = c * BK;
#pragma unroll
        for (int j = 0; j < 2; j++) {
            int idx = tid + j * 256;
            int row = idx >> 2, q = idx & 3;
            int r = m0 + row; if (r >= end) r = end - 1;
            cpa16(base + (uint32_t)(row * (TS * 2) + q * 16),
                  g_h16 + (size_t)r * K + k0 + q * 8);
        }
#pragma unroll
        for (int j = 0; j < 2; j++) {
            int idx = tid + j * 256;
            int kr = idx >> 4, q = idx & 15;
            cpa16(base + A_TILE_B + (uint32_t)(kr * (BS * 2) + q * 16),
                  Bm + (size_t)(k0 + kr) * N + q * 8);
        }
        cpa_commit();
    };

    float acc[2][8][4];
#pragma unroll
    for (int mf = 0; mf < 2; mf++)
#pragma unroll
        for (int nf = 0; nf < 8; nf++)
#pragma unroll
            for (int i = 0; i < 4; i++) acc[mf][nf][i] = 0.0f;

    load_chunk(0);
    load_chunk(1);

    for (int c = 0; c < NCH; c++) {
        if (c + 2 < NCH)      { load_chunk(c + 2); cpa_wait<2>(); }
        else if (c + 1 < NCH) { cpa_wait<1>(); }
        else                  { cpa_wait<0>(); }
        __syncthreads();

        uint32_t stA = sb + (uint32_t)(c % NSTAGE) * DN_STAGE;
        uint32_t stB = stA + A_TILE_B;

#pragma unroll
        for (int ks = 0; ks < 2; ks++) {
            int kb = ks * 16;
            uint32_t a[2][4];
#pragma unroll
            for (int mf = 0; mf < 2; mf++)
                ldm_x4(a[mf], stA + (uint32_t)(((wm + mf * 16 + a_row) * TS + kb + a_koff) * 2));

            int bk = kb + b_krow;
#pragma unroll
            for (int pf = 0; pf < 4; pf++) {
                int bn = wn + pf * 16 + b_noff;
                uint32_t b[4];
                ldm_x4_t(b, stB + (uint32_t)((bk * BS + bn) * 2));
#pragma unroll
                for (int sub = 0; sub < 2; sub++) {
                    int nf = pf * 2 + sub;
#pragma unroll
                    for (int mf = 0; mf < 2; mf++)
                        mma16(acc[mf][nf], a[mf], b + sub * 2);
                }
            }
        }
        __syncthreads();
    }

#pragma unroll
    for (int mf = 0; mf < 2; mf++) {
#pragma unroll
        for (int nf = 0; nf < 8; nf++) {
            int row0 = m0 + wm + mf * 16 + gr;
            int col  = n0 + wn + nf * 8 + qc;
            if (row0 < end)
                *(float2*)(g_y + (size_t)row0 * N + col) =
                    make_float2(acc[mf][nf][0], acc[mf][nf][1]);
            int row1 = row0 + 8;
            if (row1 < end)
                *(float2*)(g_y + (size_t)row1 * N + col) =
                    make_float2(acc[mf][nf][2], acc[mf][nf][3]);
        }
    }
}

// ---------------------------------------------------------------------------
// Combine: out[t] = w0 * y[p0] + w1 * y[p1]
// ---------------------------------------------------------------------------
__global__ void combine_kernel(float* __restrict__ out) {
    int t = blockIdx.x;
    int p0 = g_pos[2 * t], p1 = g_pos[2 * t + 1];
    float w0 = g_topW[2 * t], w1 = g_topW[2 * t + 1];
    const float4* y0 = (const float4*)(g_y + (size_t)p0 * H_DIM);
    const float4* y1 = (const float4*)(g_y + (size_t)p1 * H_DIM);
    float4* o = (float4*)(out + (size_t)t * H_DIM);
    float4 a = y0[threadIdx.x], b = y1[threadIdx.x];
    float4 v;
    v.x = w0 * a.x + w1 * b.x;
    v.y = w0 * a.y + w1 * b.y;
    v.z = w0 * a.z + w1 * b.z;
    v.w = w0 * a.w + w1 * b.w;
    o[threadIdx.x] = v;
}

// ---------------------------------------------------------------------------
extern "C" void kernel_launch(void* const* d_in, const int* in_sizes, int n_in,
                              void* d_out, int out_size) {
    const float* x   = (const float*)d_in[0];
    const float* wg  = (const float*)d_in[1];
    const float* wgp = (const float*)d_in[2];
    const float* wup = (const float*)d_in[3];
    const float* wdp = (const float*)d_in[4];
    float* out = (float*)d_out;

    int T = in_sizes[0] / H_DIM;   // 4096

    cudaFuncSetAttribute(gateup_kernel,
                         cudaFuncAttributeMaxDynamicSharedMemorySize, NSTAGE * GU_STAGE);
    cudaFuncSetAttribute(down_kernel,
                         cudaFuncAttributeMaxDynamicSharedMemorySize, NSTAGE * DN_STAGE);

    zero_kernel<<<1, 32>>>();
    router_kernel<<<(T + 7) / 8, 256>>>(x, wg, T);
    offsets_kernel<<<1, 1>>>();
    scatter_kernel<<<(2 * T + 255) / 256, 256>>>(T);
    gather_kernel<<<2 * T, 256>>>(x);

    {
        int nblk = (N_EXP * H_DIM * F_DIM) / (256 * 8);   // 16384
        convert_kernel<0><<<nblk, 256>>>((const float4*)wgp);
        convert_kernel<1><<<nblk, 256>>>((const float4*)wup);
        convert_kernel<2><<<nblk, 256>>>((const float4*)wdp);
    }

    dim3 g1(F_DIM / BN, (T + BM - 1) / BM, N_EXP);
    gateup_kernel<<<g1, 256, NSTAGE * GU_STAGE>>>();

    dim3 g2(H_DIM / BN, (T + BM - 1) / BM, N_EXP);
    down_kernel<<<g2, 256, NSTAGE * DN_STAGE>>>();

    combine_kernel<<<T, 256>>>(out);
}